// round 14
// baseline (speedup 1.0000x reference)
#include <cuda_runtime.h>
#include <cstdint>

// GIKDWConv: depthwise 7x7 conv, stride 1, pad 3, 4-fold-rotation-symmetrized
// weights. N=16, C=384, H=W=64, fp32.
//
// R14: uniform half-size blocks. One block = one (n, channel-pair, 32-row
// half): 6144 identical blocks -> wave drain ~0.7*T_half (~4us saved vs
// R12's 0.85*T_b). Single 38x70 smem buffer, cp.async burst prologue (the
// ~25% exposure is hidden by the 4 other desynced CTAs per SM). Compute
// core identical to R12: 8 rows x 2 cols per thread, channel pairs packed
// in f32x2, C4 pair-sum factored filter (40 FFMA2 + shared FADD2 per
// output), 13 unique symmetrized weights in registers, 5 CTAs/SM.

#define HH 64
#define WW 64
#define NN 16
#define CC 384
#define TR 38              // tile rows: 32 output + 6 halo
#define TC 70              // tile cols: 64 output + 6 halo
#define CELLS (TR * TC)    // 2660
#define NSLICE 21          // ceil(2660/128)
#define RPT 8              // output rows per thread
typedef unsigned long long ull;

__device__ constexpr int REP_I[13] = {0,0,0,0,0,0,1,1,1,1,2,2,3};
__device__ constexpr int REP_J[13] = {0,1,2,3,4,5,1,2,3,4,2,3,3};

// factored row formulas: per k, up to 6 (coef, src) terms.
// src indexes: 0=u06, 1..5 = x1..x5, 6=x0, 7=x6, 8=u15, 9=u24
__device__ constexpr int KNT[7]      = {6,6,6,4,6,6,6};
__device__ constexpr int KC[7][6] = {
    {0, 1, 2, 3, 4, 5},
    {6, 5, 7, 8, 9, 1},
    {10,4, 9, 11,7, 2},
    {3, 8, 11,12,0, 0},
    {10,2, 7, 11,9, 4},
    {6, 1, 9, 8, 7, 5},
    {0, 5, 4, 3, 2, 1}};
__device__ constexpr int KS[7][6] = {
    {0, 1, 2, 3, 4, 5},
    {8, 6, 2, 3, 4, 7},
    {9, 6, 1, 3, 5, 7},
    {0, 8, 9, 3, 0, 0},
    {9, 6, 1, 3, 5, 7},
    {8, 6, 2, 3, 4, 7},
    {0, 1, 2, 3, 4, 5}};

__device__ __forceinline__ ull fma2(ull a, ull b, ull c) {
    ull d;
    asm("fma.rn.f32x2 %0, %1, %2, %3;" : "=l"(d) : "l"(a), "l"(b), "l"(c));
    return d;
}
__device__ __forceinline__ ull add2(ull a, ull b) {
    ull d;
    asm("add.rn.f32x2 %0, %1, %2;" : "=l"(d) : "l"(a), "l"(b));
    return d;
}
__device__ __forceinline__ ull pack2(float lo, float hi) {
    ull r;
    asm("mov.b64 %0, {%1, %2};" : "=l"(r) : "f"(lo), "f"(hi));
    return r;
}
__device__ __forceinline__ void unpack2(ull v, float& lo, float& hi) {
    asm("mov.b64 {%0, %1}, %2;" : "=f"(lo), "=f"(hi) : "l"(v));
}
__device__ __forceinline__ uint32_t s2u(const void* p) {
    uint32_t a;
    asm("{ .reg .u64 t; cvta.to.shared.u64 t, %1; cvt.u32.u64 %0, t; }"
        : "=r"(a) : "l"(p));
    return a;
}
// 4-byte cp.async with zfill: sz=4 copies, sz=0 writes zeros (no src access)
__device__ __forceinline__ void cp4(uint32_t d, const float* s, int sz) {
    asm volatile("cp.async.ca.shared.global [%0], [%1], 4, %2;"
                 :: "r"(d), "l"(s), "r"(sz));
}

__global__ __launch_bounds__(128, 5)
void gik_dwconv_kernel(const float* __restrict__ x,
                       const float* __restrict__ weight,
                       float* __restrict__ out) {
    __shared__ ull sx[CELLS];       // packed (c0,c1) half-tile, 21.3 KB
    __shared__ ull sw[13];          // packed symmetric weights

    const int tid  = threadIdx.x;
    const int cp   = blockIdx.x;        // channel pair 0..191
    const int n    = blockIdx.y;        // batch 0..15
    const int half = blockIdx.z;        // vertical half 0..1
    const int c0   = cp * 2;

    const float* x0 = x + ((n * CC + c0) * (HH * WW));
    const float* x1 = x0 + HH * WW;
    const uint32_t sbase = s2u(sx);

    // ---- burst prologue: load this half's 38x70 tile ----
    const int gy0 = half * 32 - 3;
    #pragma unroll
    for (int s = 0; s < NSLICE; s++) {
        int cell = s * 128 + tid;
        if (cell < CELLS) {
            int r  = cell / TC;
            int c  = cell - r * TC;
            int gy = gy0 + r, gx = c - 3;
            int v  = ((unsigned)gy < (unsigned)HH) &
                     ((unsigned)gx < (unsigned)WW);
            int off = v ? (gy * WW + gx) : 0;
            int sz  = v ? 4 : 0;
            cp4(sbase + cell * 8,     x0 + off, sz);
            cp4(sbase + cell * 8 + 4, x1 + off, sz);
        }
    }
    asm volatile("cp.async.commit_group;" ::: "memory");

    // ---- the 13 unique symmetrized weights (LDG overlaps the cp.async) ----
    if (tid < 13) {
        const int i = REP_I[tid], j = REP_J[tid];
        const float* w0 = weight + c0 * 49;
        const float* w1 = w0 + 49;
        float a0 = 0.25f * (w0[i*7 + j] + w0[j*7 + (6-i)] +
                            w0[(6-i)*7 + (6-j)] + w0[(6-j)*7 + i]);
        float a1 = 0.25f * (w1[i*7 + j] + w1[j*7 + (6-i)] +
                            w1[(6-i)*7 + (6-j)] + w1[(6-j)*7 + i]);
        sw[tid] = pack2(a0, a1);
    }

    const int cx = (tid & 31) * 2;     // even output column 0..62
    const int r0 = (tid >> 5) * RPT;   // local output row base: 0,8,16,24

    asm volatile("cp.async.wait_group 0;" ::: "memory");
    __syncthreads();                   // tile + weights visible

    ull wreg[13];
    #pragma unroll
    for (int o = 0; o < 13; o++) wreg[o] = sw[o];

    ull acc0[RPT], acc1[RPT];          // col cx and cx+1
    #pragma unroll
    for (int r = 0; r < RPT; r++) { acc0[r] = 0ull; acc1[r] = 0ull; }

    #pragma unroll
    for (int y = 0; y < RPT + 6; y++) {
        ull xv[8];                     // 8 packed inputs: 4x LDS.128
        {
            const ulonglong2* rp =
                (const ulonglong2*)(sx + (r0 + y) * TC + cx);
            #pragma unroll
            for (int q = 0; q < 4; q++) {
                ulonglong2 v = rp[q];
                xv[2*q] = v.x; xv[2*q+1] = v.y;
            }
        }
        // shared pair-sums (FADD2) for cols A (cx) and B (cx+1)
        ull sA[10], sB[10];
        sA[0] = add2(xv[0], xv[6]);  sB[0] = add2(xv[1], xv[7]);  // u06
        sA[8] = add2(xv[1], xv[5]);  sB[8] = add2(xv[2], xv[6]);  // u15
        sA[9] = add2(xv[2], xv[4]);  sB[9] = add2(xv[3], xv[5]);  // u24
        sA[1]=xv[1]; sA[2]=xv[2]; sA[3]=xv[3]; sA[4]=xv[4];
        sA[5]=xv[5]; sA[6]=xv[0]; sA[7]=xv[6];
        sB[1]=xv[2]; sB[2]=xv[3]; sB[3]=xv[4]; sB[4]=xv[5];
        sB[5]=xv[6]; sB[6]=xv[1]; sB[7]=xv[7];

        #pragma unroll
        for (int k = 0; k < 7; k++) {
            const int r = y - k;
            if (r >= 0 && r < RPT) {
                #pragma unroll
                for (int u = 0; u < 6; u++) {
                    if (u < KNT[k]) {
                        const ull w = wreg[KC[k][u]];
                        acc0[r] = fma2(w, sA[KS[k][u]], acc0[r]);
                        acc1[r] = fma2(w, sB[KS[k][u]], acc1[r]);
                    }
                }
            }
        }
    }

    // ---- store: float2 per channel-row ----
    float* o0 = out + ((n * CC + c0) * (HH * WW)) + half * 32 * WW;
    float* o1 = o0 + HH * WW;
    #pragma unroll
    for (int r = 0; r < RPT; r++) {
        float a, b, c, d;
        unpack2(acc0[r], a, b);         // a: c0 col cx,   b: c1 col cx
        unpack2(acc1[r], c, d);         // c: c0 col cx+1, d: c1 col cx+1
        const int off = (r0 + r) * WW + cx;
        *(float2*)(o0 + off) = make_float2(a, c);
        *(float2*)(o1 + off) = make_float2(b, d);
    }
}

extern "C" void kernel_launch(void* const* d_in, const int* in_sizes, int n_in,
                              void* d_out, int out_size) {
    const float* x = (const float*)d_in[0];       // [16,384,64,64]
    const float* w = (const float*)d_in[1];       // [384,1,7,7]
    float* out = (float*)d_out;                   // [16,384,64,64]
    dim3 grid(CC / 2, NN, 2);
    gik_dwconv_kernel<<<grid, 128>>>(x, w, out);
}

// round 15
// speedup vs baseline: 1.1783x; 1.1783x over previous
#include <cuda_runtime.h>
#include <cstdint>

// GIKDWConv: depthwise 7x7 conv, stride 1, pad 3, 4-fold-rotation-symmetrized
// weights. N=16, C=384, H=W=64, fp32.
//
// R15: R12 (best: 53.7us) with the tile-loader addressing made incremental.
// Each cp.async slice previously recomputed cell/70 (mulhi+shift), mod,
// bounds and addresses (~13 ALU inst/slice x 42 slices/thread). Now a
// carried (r, c, dst) state advances by +128 cells per slice with two adds
// and a compare (~7 inst/slice), cutting ~250 issue slots per thread from
// the stream that competes with FFMA2 issue. Pipeline, factored C4 math
// (40 FFMA2 + shared FADD2 per row per 2 cols), grid and residency are
// identical to R12.

#define HH 64
#define WW 64
#define NN 16
#define CC 384
#define TR 38              // tile rows: 32 output + 6 halo
#define TC 70              // tile cols: 64 output + 6 halo
#define CELLS (TR * TC)    // 2660
#define NSLICE 21          // ceil(2660/128)
#define RPT 8              // output rows per thread
typedef unsigned long long ull;

__device__ constexpr int REP_I[13] = {0,0,0,0,0,0,1,1,1,1,2,2,3};
__device__ constexpr int REP_J[13] = {0,1,2,3,4,5,1,2,3,4,2,3,3};

// factored row formulas: per k, up to 6 (coef, src) terms.
// src indexes: 0=u06, 1..5 = x1..x5, 6=x0, 7=x6, 8=u15, 9=u24
__device__ constexpr int KNT[7]      = {6,6,6,4,6,6,6};
__device__ constexpr int KC[7][6] = {
    {0, 1, 2, 3, 4, 5},
    {6, 5, 7, 8, 9, 1},
    {10,4, 9, 11,7, 2},
    {3, 8, 11,12,0, 0},
    {10,2, 7, 11,9, 4},
    {6, 1, 9, 8, 7, 5},
    {0, 5, 4, 3, 2, 1}};
__device__ constexpr int KS[7][6] = {
    {0, 1, 2, 3, 4, 5},
    {8, 6, 2, 3, 4, 7},
    {9, 6, 1, 3, 5, 7},
    {0, 8, 9, 3, 0, 0},
    {9, 6, 1, 3, 5, 7},
    {8, 6, 2, 3, 4, 7},
    {0, 1, 2, 3, 4, 5}};

__device__ __forceinline__ ull fma2(ull a, ull b, ull c) {
    ull d;
    asm("fma.rn.f32x2 %0, %1, %2, %3;" : "=l"(d) : "l"(a), "l"(b), "l"(c));
    return d;
}
__device__ __forceinline__ ull add2(ull a, ull b) {
    ull d;
    asm("add.rn.f32x2 %0, %1, %2;" : "=l"(d) : "l"(a), "l"(b));
    return d;
}
__device__ __forceinline__ ull pack2(float lo, float hi) {
    ull r;
    asm("mov.b64 %0, {%1, %2};" : "=l"(r) : "f"(lo), "f"(hi));
    return r;
}
__device__ __forceinline__ void unpack2(ull v, float& lo, float& hi) {
    asm("mov.b64 {%0, %1}, %2;" : "=f"(lo), "=f"(hi) : "l"(v));
}
__device__ __forceinline__ uint32_t s2u(const void* p) {
    uint32_t a;
    asm("{ .reg .u64 t; cvta.to.shared.u64 t, %1; cvt.u32.u64 %0, t; }"
        : "=r"(a) : "l"(p));
    return a;
}
// 4-byte cp.async with zfill: sz=4 copies, sz=0 writes zeros (no src access)
__device__ __forceinline__ void cp4(uint32_t d, const float* s, int sz) {
    asm volatile("cp.async.ca.shared.global [%0], [%1], 4, %2;"
                 :: "r"(d), "l"(s), "r"(sz));
}

// incremental slice cursor: this thread's cell walks +128 per slice
struct PF {
    int r, c;          // tile coords of this thread's cell
    uint32_t dst;      // smem address of that cell
    __device__ __forceinline__ void init(int tid, uint32_t base) {
        r = (tid >= TC) ? 1 : 0;
        c = tid - r * TC;
        dst = base + (uint32_t)tid * 8u;
    }
    __device__ __forceinline__ void advance() {
        c += 128 - TC; r += 1;
        if (c >= TC) { c -= TC; r += 1; }
        dst += 128 * 8;
    }
    // issue the 2 cp.async for this cell (guard r < TR for the ragged tail)
    __device__ __forceinline__ void issue(const float* x0, const float* x1,
                                          int gy0) const {
        if (r < TR) {
            int gy = gy0 + r, gx = c - 3;
            int v  = ((unsigned)gy < (unsigned)HH) &
                     ((unsigned)gx < (unsigned)WW);
            int off = v ? (gy * WW + gx) : 0;
            int sz  = v ? 4 : 0;
            cp4(dst,     x0 + off, sz);
            cp4(dst + 4, x1 + off, sz);
        }
    }
};

__global__ __launch_bounds__(128, 5)
void gik_dwconv_kernel(const float* __restrict__ x,
                       const float* __restrict__ weight,
                       float* __restrict__ out) {
    __shared__ ull sx[2 * CELLS];   // double-buffered packed half-tiles
    __shared__ ull sw[13];          // packed symmetric weights

    const int tid = threadIdx.x;
    const int cp  = blockIdx.x;         // channel pair 0..191
    const int n   = blockIdx.y;         // batch 0..15
    const int c0  = cp * 2;

    const float* x0 = x + ((n * CC + c0) * (HH * WW));
    const float* x1 = x0 + HH * WW;
    const uint32_t sbase = s2u(sx);

    // ---- prologue: load half 0 into buffer 0 (incremental cursor) ----
    {
        PF pf; pf.init(tid, sbase);
        #pragma unroll
        for (int s = 0; s < NSLICE; s++) {
            pf.issue(x0, x1, -3);
            pf.advance();
        }
        asm volatile("cp.async.commit_group;" ::: "memory");
    }

    // ---- the 13 unique symmetrized weights (LDG overlaps the cp.async) ----
    if (tid < 13) {
        const int i = REP_I[tid], j = REP_J[tid];
        const float* w0 = weight + c0 * 49;
        const float* w1 = w0 + 49;
        float a0 = 0.25f * (w0[i*7 + j] + w0[j*7 + (6-i)] +
                            w0[(6-i)*7 + (6-j)] + w0[(6-j)*7 + i]);
        float a1 = 0.25f * (w1[i*7 + j] + w1[j*7 + (6-i)] +
                            w1[(6-i)*7 + (6-j)] + w1[(6-j)*7 + i]);
        sw[tid] = pack2(a0, a1);
    }

    const int cx = (tid & 31) * 2;     // even output column 0..62
    const int r0 = (tid >> 5) * RPT;   // local output row base: 0,8,16,24

    asm volatile("cp.async.wait_group 0;" ::: "memory");
    __syncthreads();                   // half 0 + weights visible

    ull wreg[13];
    #pragma unroll
    for (int o = 0; o < 13; o++) wreg[o] = sw[o];

    PF pf; pf.init(tid, sbase + CELLS * 8);   // cursor for half-1 prefetch

    #pragma unroll
    for (int t = 0; t < 2; t++) {
        const ull* sb = sx + t * CELLS;

        ull acc0[RPT], acc1[RPT];      // col cx and cx+1
        #pragma unroll
        for (int r = 0; r < RPT; r++) { acc0[r] = 0ull; acc1[r] = 0ull; }

        #pragma unroll
        for (int y = 0; y < RPT + 6; y++) {
            ull xv[8];                 // 8 packed inputs: 4x LDS.128
            {
                const ulonglong2* rp =
                    (const ulonglong2*)(sb + (r0 + y) * TC + cx);
                #pragma unroll
                for (int q = 0; q < 4; q++) {
                    ulonglong2 v = rp[q];
                    xv[2*q] = v.x; xv[2*q+1] = v.y;
                }
            }
            // front-loaded prefetch of half 1 (t=0): 3 slices/iter, y<7
            if (t == 0 && y < 7) {
                pf.issue(x0, x1, 29); pf.advance();
                pf.issue(x0, x1, 29); pf.advance();
                pf.issue(x0, x1, 29); pf.advance();
                if (y == 6)
                    asm volatile("cp.async.commit_group;" ::: "memory");
            }
            // shared pair-sums (FADD2) for cols A (cx) and B (cx+1)
            ull sA[10], sB[10];
            sA[0] = add2(xv[0], xv[6]);  sB[0] = add2(xv[1], xv[7]);  // u06
            sA[8] = add2(xv[1], xv[5]);  sB[8] = add2(xv[2], xv[6]);  // u15
            sA[9] = add2(xv[2], xv[4]);  sB[9] = add2(xv[3], xv[5]);  // u24
            sA[1]=xv[1]; sA[2]=xv[2]; sA[3]=xv[3]; sA[4]=xv[4];
            sA[5]=xv[5]; sA[6]=xv[0]; sA[7]=xv[6];
            sB[1]=xv[2]; sB[2]=xv[3]; sB[3]=xv[4]; sB[4]=xv[5];
            sB[5]=xv[6]; sB[6]=xv[1]; sB[7]=xv[7];

            #pragma unroll
            for (int k = 0; k < 7; k++) {
                const int r = y - k;
                if (r >= 0 && r < RPT) {
                    #pragma unroll
                    for (int u = 0; u < 6; u++) {
                        if (u < KNT[k]) {
                            const ull w = wreg[KC[k][u]];
                            acc0[r] = fma2(w, sA[KS[k][u]], acc0[r]);
                            acc1[r] = fma2(w, sB[KS[k][u]], acc1[r]);
                        }
                    }
                }
            }
        }

        // ---- store: float2 per channel-row ----
        float* o0 = out + ((n * CC + c0) * (HH * WW)) + t * 32 * WW;
        float* o1 = o0 + HH * WW;
        #pragma unroll
        for (int r = 0; r < RPT; r++) {
            float a, b, c, d;
            unpack2(acc0[r], a, b);     // a: c0 col cx,   b: c1 col cx
            unpack2(acc1[r], c, d);     // c: c0 col cx+1, d: c1 col cx+1
            const int off = (r0 + r) * WW + cx;
            *(float2*)(o0 + off) = make_float2(a, c);
            *(float2*)(o1 + off) = make_float2(b, d);
        }
        if (t == 0) {
            asm volatile("cp.async.wait_group 0;" ::: "memory");
            __syncthreads();           // half 1 fully resident in buffer 1
        }
    }
}

extern "C" void kernel_launch(void* const* d_in, const int* in_sizes, int n_in,
                              void* d_out, int out_size) {
    const float* x = (const float*)d_in[0];       // [16,384,64,64]
    const float* w = (const float*)d_in[1];       // [384,1,7,7]
    float* out = (float*)d_out;                   // [16,384,64,64]
    dim3 grid(CC / 2, NN);
    gik_dwconv_kernel<<<grid, 128>>>(x, w, out);
}